// round 15
// baseline (speedup 1.0000x reference)
#include <cuda_runtime.h>

#define N_BINS 15
#define GRID   296          // 2 CTAs/SM x 148 SMs, single wave
#define TPB    256
#define WARPS  (TPB / 32)

// Global accumulators. Zero at module load; the LAST block resets them
// after consuming, so every graph replay starts clean.
__device__ float    g_acc_conf[16];
__device__ float    g_acc_corr[16];
__device__ unsigned g_done = 0;

// Guaranteed-MUFU exp2.
__device__ __forceinline__ float ex2(float t) {
    float r;
    asm("ex2.approx.f32 %0, %1;" : "=f"(r) : "f"(t));
    return r;
}

#define L2E 1.4426950408889634f   // log2(e)

// Per-row core: exps at 2^21 scale, local max/sum, label e-value.
__device__ __forceinline__ void row_core(
    const float4& v, int lbl, int lane,
    float& em, float& s, float& ev, bool& isLabLane)
{
    float e0 = ex2(fmaf(v.x, L2E, 21.0f));
    float e1 = ex2(fmaf(v.y, L2E, 21.0f));
    float e2 = ex2(fmaf(v.z, L2E, 21.0f));
    float e3 = ex2(fmaf(v.w, L2E, 21.0f));
    em = fmaxf(fmaxf(e0, e1), fmaxf(e2, e3));
    s  = (e0 + e1) + (e2 + e3);
    int ci = lbl & 3;
    ev = (ci == 0) ? e0 : (ci == 1) ? e1 : (ci == 2) ? e2 : e3;
    isLabLane = (lane == (lbl >> 2));
}

// Post-reduction per-row epilogue (conf, bin, atomics).
__device__ __forceinline__ void row_tail(
    int km, unsigned S, float ev, bool ll, int lane, int confLane,
    float* sConf, float* sCorr)
{
    float conf = __fdividef(__int_as_float(km), (float)S);
    // bin i holds conf in (i/15,(i+1)/15] -> ceil(conf*15)-1; b>=0 proven.
    int b = min(__float2int_ru(conf * 15.0f) - 1, 14);
    if (lane == confLane) atomicAdd(&sConf[b], conf);
    // argmax == label <=> label e bits == max bits (ties measure-zero).
    if (ll && __float_as_int(ev) == km) atomicAdd(&sCorr[b], 1.0f);
}

// Warp handles EIGHT adjacent rows per iteration (N % 8 tail done separately).
__global__ void __launch_bounds__(TPB, 2) ece_fused(
    const float* __restrict__ logits,
    const int* __restrict__ labels,   // JAX x64-off: int64 demoted to int32
    int N,
    float* __restrict__ out)
{
    __shared__ float sConf[16];
    __shared__ float sCorr[16];
    __shared__ unsigned sTicket;

    const int tid  = threadIdx.x;
    const int lane = tid & 31;
    const int warp = tid >> 5;
    const bool active = (lane < 25);
    const float NEG_INF = __int_as_float(0xff800000);
    const float4 NEG4 = make_float4(NEG_INF, NEG_INF, NEG_INF, NEG_INF);

    if (tid < N_BINS) { sConf[tid] = 0.0f; sCorr[tid] = 0.0f; }
    __syncthreads();

    const int gwarp  = blockIdx.x * WARPS + warp;
    const int nwarps = GRID * WARPS;
    const int nOcts  = N >> 3;          // full groups of 8 rows

    const float4* p     = (const float4*)logits + (size_t)gwarp * 200;
    const size_t  pstep = (size_t)nwarps * 200;

    // Prefetch first oct.
    float4 A = NEG4, B = NEG4, C = NEG4, D = NEG4;
    float4 E = NEG4, F = NEG4, G = NEG4, H = NEG4;
    int4 L0 = make_int4(0,0,0,0), L1 = make_int4(0,0,0,0);
    int o = gwarp;
    if (o < nOcts) {
        if (active) {
            A = __ldg(p + lane);        B = __ldg(p +  25 + lane);
            C = __ldg(p +  50 + lane);  D = __ldg(p +  75 + lane);
            E = __ldg(p + 100 + lane);  F = __ldg(p + 125 + lane);
            G = __ldg(p + 150 + lane);  H = __ldg(p + 175 + lane);
        }
        L0 = __ldg((const int4*)labels + 2 * o);
        L1 = __ldg((const int4*)labels + 2 * o + 1);
    }

    for (; o < nOcts; o += nwarps, p += pstep) {
        // Consume prefetched oct immediately (prefetch registers die here).
        float emA,sA,evA; bool llA;  float emB,sB,evB; bool llB;
        float emC,sC,evC; bool llC;  float emD,sD,evD; bool llD;
        float emE,sE,evE; bool llE;  float emF,sF,evF; bool llF;
        float emG,sG,evG; bool llG;  float emH,sH,evH; bool llH;
        row_core(A, L0.x, lane, emA, sA, evA, llA);
        row_core(B, L0.y, lane, emB, sB, evB, llB);
        row_core(C, L0.z, lane, emC, sC, evC, llC);
        row_core(D, L0.w, lane, emD, sD, evD, llD);
        row_core(E, L1.x, lane, emE, sE, evE, llE);
        row_core(F, L1.y, lane, emF, sF, evF, llF);
        row_core(G, L1.z, lane, emG, sG, evG, llG);
        row_core(H, L1.w, lane, emH, sH, evH, llH);
        int4 l0 = L0, l1 = L1; (void)l0; (void)l1;

        // Prefetch next oct (overlaps the reductions below).
        int no = o + nwarps;
        if (no < nOcts) {
            if (active) {
                A = __ldg(p + pstep + lane);        B = __ldg(p + pstep +  25 + lane);
                C = __ldg(p + pstep +  50 + lane);  D = __ldg(p + pstep +  75 + lane);
                E = __ldg(p + pstep + 100 + lane);  F = __ldg(p + pstep + 125 + lane);
                G = __ldg(p + pstep + 150 + lane);  H = __ldg(p + pstep + 175 + lane);
            }
            L0 = __ldg((const int4*)labels + 2 * no);
            L1 = __ldg((const int4*)labels + 2 * no + 1);
        }

        // 16 interleaved warp reductions (8-deep MIO latency hiding).
        int kmA = __reduce_max_sync(0xffffffffu, __float_as_int(emA));
        int kmB = __reduce_max_sync(0xffffffffu, __float_as_int(emB));
        int kmC = __reduce_max_sync(0xffffffffu, __float_as_int(emC));
        int kmD = __reduce_max_sync(0xffffffffu, __float_as_int(emD));
        int kmE = __reduce_max_sync(0xffffffffu, __float_as_int(emE));
        int kmF = __reduce_max_sync(0xffffffffu, __float_as_int(emF));
        int kmG = __reduce_max_sync(0xffffffffu, __float_as_int(emG));
        int kmH = __reduce_max_sync(0xffffffffu, __float_as_int(emH));
        unsigned SA = __reduce_add_sync(0xffffffffu, __float2uint_rn(sA));
        unsigned SB = __reduce_add_sync(0xffffffffu, __float2uint_rn(sB));
        unsigned SC = __reduce_add_sync(0xffffffffu, __float2uint_rn(sC));
        unsigned SD = __reduce_add_sync(0xffffffffu, __float2uint_rn(sD));
        unsigned SE = __reduce_add_sync(0xffffffffu, __float2uint_rn(sE));
        unsigned SF = __reduce_add_sync(0xffffffffu, __float2uint_rn(sF));
        unsigned SG = __reduce_add_sync(0xffffffffu, __float2uint_rn(sG));
        unsigned SH = __reduce_add_sync(0xffffffffu, __float2uint_rn(sH));

        row_tail(kmA, SA, evA, llA, lane, 0, sConf, sCorr);
        row_tail(kmB, SB, evB, llB, lane, 1, sConf, sCorr);
        row_tail(kmC, SC, evC, llC, lane, 2, sConf, sCorr);
        row_tail(kmD, SD, evD, llD, lane, 3, sConf, sCorr);
        row_tail(kmE, SE, evE, llE, lane, 4, sConf, sCorr);
        row_tail(kmF, SF, evF, llF, lane, 5, sConf, sCorr);
        row_tail(kmG, SG, evG, llG, lane, 6, sConf, sCorr);
        row_tail(kmH, SH, evH, llH, lane, 7, sConf, sCorr);
    }

    // ---- generic-N tail: rows [nOcts*8, N), warp-per-row (never runs
    //      when N % 8 == 0, e.g. N = 1e6) ----
    int tailBase = nOcts << 3;
    int tailCnt  = N - tailBase;
    if (gwarp < tailCnt) {
        int row = tailBase + gwarp;
        float4 v = NEG4;
        if (active)
            v = __ldg((const float4*)logits + (size_t)row * 25 + lane);
        int lbl = __ldg(labels + row);
        float em, s, ev; bool ll;
        row_core(v, lbl, lane, em, s, ev, ll);
        int km = __reduce_max_sync(0xffffffffu, __float_as_int(em));
        unsigned S = __reduce_add_sync(0xffffffffu, __float2uint_rn(s));
        row_tail(km, S, ev, ll, lane, 0, sConf, sCorr);
    }

    // ---- block tail: partials -> global accumulators ----
    __syncthreads();
    if (tid < N_BINS) {
        atomicAdd(&g_acc_conf[tid], sConf[tid]);
        atomicAdd(&g_acc_corr[tid], sCorr[tid]);
    }
    __threadfence();                      // publish before ticket
    if (tid == 0) sTicket = atomicAdd(&g_done, 1u);
    __syncthreads();

    // ---- last block finalizes, writes out, resets for next replay ----
    if (sTicket == GRID - 1) {
        __threadfence();                  // acquire: see all blocks' adds
        if (tid == 0) {
            float s = 0.0f;
            #pragma unroll
            for (int i = 0; i < N_BINS; i++)
                s += fabsf(g_acc_conf[i] - g_acc_corr[i]);
            out[0] = s / (float)N;

            #pragma unroll
            for (int i = 0; i < 16; i++) {
                g_acc_conf[i] = 0.0f;
                g_acc_corr[i] = 0.0f;
            }
            g_done = 0;                   // clean state for next graph replay
        }
    }
}

extern "C" void kernel_launch(void* const* d_in, const int* in_sizes, int n_in,
                              void* d_out, int out_size)
{
    const float* logits = (const float*)d_in[0];
    const int*   labels = (const int*)d_in[1];
    const int N = in_sizes[1];          // label count = number of rows

    ece_fused<<<GRID, TPB>>>(logits, labels, N, (float*)d_out);
}

// round 16
// speedup vs baseline: 1.0165x; 1.0165x over previous
#include <cuda_runtime.h>

#define N_BINS 15
#define GRID   444          // 3 CTAs/SM x 148 SMs, single wave
#define TPB    256
#define WARPS  (TPB / 32)
#define RPG    6            // rows per group

// Global diff accumulator (conf - correct), per bin. Zero at module load;
// the LAST block resets after consuming -> clean for every graph replay.
__device__ float    g_acc_diff[16];
__device__ unsigned g_done = 0;

// Guaranteed-MUFU exp2.
__device__ __forceinline__ float ex2(float t) {
    float r;
    asm("ex2.approx.f32 %0, %1;" : "=f"(r) : "f"(t));
    return r;
}

#define L2E 1.4426950408889634f   // log2(e)

// Per-row core: exps at 2^21 scale, local max/sum, label e-value.
__device__ __forceinline__ void row_core(
    const float4& v, int lbl, int lane,
    float& em, float& s, float& ev, bool& isLabLane)
{
    float e0 = ex2(fmaf(v.x, L2E, 21.0f));
    float e1 = ex2(fmaf(v.y, L2E, 21.0f));
    float e2 = ex2(fmaf(v.z, L2E, 21.0f));
    float e3 = ex2(fmaf(v.w, L2E, 21.0f));
    em = fmaxf(fmaxf(e0, e1), fmaxf(e2, e3));
    s  = (e0 + e1) + (e2 + e3);
    int ci = lbl & 3;
    ev = (ci == 0) ? e0 : (ci == 1) ? e1 : (ci == 2) ? e2 : e3;
    isLabLane = (lane == (lbl >> 2));   // lbl < 100 -> lane 0..24
}

// Post-reduction epilogue: ONE predicated atomic per row, on the label lane.
// Accumulates (conf - correct) -- the only quantity ECE needs per bin.
__device__ __forceinline__ void row_tail(
    int km, unsigned S, float ev, bool ll, float* sDiff)
{
    float conf = __fdividef(__int_as_float(km), (float)S);
    // bin i holds conf in (i/15,(i+1)/15] -> ceil(conf*15)-1; b>=0 proven.
    int b = min(__float2int_ru(conf * 15.0f) - 1, 14);
    // argmax == label <=> label e bits == max bits (ties measure-zero).
    float d = conf - ((__float_as_int(ev) == km) ? 1.0f : 0.0f);
    if (ll) atomicAdd(&sDiff[b], d);
}

// Warp handles SIX adjacent rows per iteration; branchless prefetch via
// clamped group index. Ragged N%6 rows handled by a tiny epilogue.
__global__ void __launch_bounds__(TPB, 3) ece_fused(
    const float* __restrict__ logits,
    const int* __restrict__ labels,   // JAX x64-off: int64 demoted to int32
    int N,
    float* __restrict__ out)
{
    __shared__ float sDiff[16];
    __shared__ unsigned sTicket;

    const int tid  = threadIdx.x;
    const int lane = tid & 31;
    const int warp = tid >> 5;
    const bool active = (lane < 25);
    const float NEG_INF = __int_as_float(0xff800000);
    const float4 NEG4 = make_float4(NEG_INF, NEG_INF, NEG_INF, NEG_INF);

    if (tid < N_BINS) sDiff[tid] = 0.0f;
    __syncthreads();

    const int gwarp  = blockIdx.x * WARPS + warp;
    const int nwarps = GRID * WARPS;
    const int nGrp   = N / RPG;         // full groups of 6 rows

    const float4* base4 = (const float4*)logits;
    const int2*   lab2  = (const int2*)labels;   // group*6 ints = 24B aligned

    // Prefetch first group. Inactive lanes hold -inf forever -> e = 0.
    float4 A = NEG4, B = NEG4, C = NEG4, D = NEG4, E = NEG4, F = NEG4;
    int2 La = make_int2(0,0), Lb = La, Lc = La;
    int g = gwarp;
    if (g < nGrp) {
        const float4* p = base4 + (size_t)g * 150;   // 6 rows = 150 float4
        if (active) {
            A = __ldg(p + lane);        B = __ldg(p +  25 + lane);
            C = __ldg(p +  50 + lane);  D = __ldg(p +  75 + lane);
            E = __ldg(p + 100 + lane);  F = __ldg(p + 125 + lane);
        }
        La = __ldg(lab2 + 3 * g);
        Lb = __ldg(lab2 + 3 * g + 1);
        Lc = __ldg(lab2 + 3 * g + 2);
    }

    for (; g < nGrp; g += nwarps) {
        // Consume prefetched group immediately (prefetch regs die here).
        float emA,sA,evA; bool llA;  float emB,sB,evB; bool llB;
        float emC,sC,evC; bool llC;  float emD,sD,evD; bool llD;
        float emE,sE,evE; bool llE;  float emF,sF,evF; bool llF;
        row_core(A, La.x, lane, emA, sA, evA, llA);
        row_core(B, La.y, lane, emB, sB, evB, llB);
        row_core(C, Lb.x, lane, emC, sC, evC, llC);
        row_core(D, Lb.y, lane, emD, sD, evD, llD);
        row_core(E, Lc.x, lane, emE, sE, evE, llE);
        row_core(F, Lc.y, lane, emF, sF, evF, llF);

        // Branchless prefetch: clamped index (last iter re-reads last group).
        int ng = min(g + nwarps, nGrp - 1);
        const float4* pn = base4 + (size_t)ng * 150;
        if (active) {
            A = __ldg(pn + lane);        B = __ldg(pn +  25 + lane);
            C = __ldg(pn +  50 + lane);  D = __ldg(pn +  75 + lane);
            E = __ldg(pn + 100 + lane);  F = __ldg(pn + 125 + lane);
        }
        La = __ldg(lab2 + 3 * ng);
        Lb = __ldg(lab2 + 3 * ng + 1);
        Lc = __ldg(lab2 + 3 * ng + 2);

        // 12 interleaved warp reductions (6-deep MIO latency hiding).
        int kmA = __reduce_max_sync(0xffffffffu, __float_as_int(emA));
        int kmB = __reduce_max_sync(0xffffffffu, __float_as_int(emB));
        int kmC = __reduce_max_sync(0xffffffffu, __float_as_int(emC));
        int kmD = __reduce_max_sync(0xffffffffu, __float_as_int(emD));
        int kmE = __reduce_max_sync(0xffffffffu, __float_as_int(emE));
        int kmF = __reduce_max_sync(0xffffffffu, __float_as_int(emF));
        unsigned SA = __reduce_add_sync(0xffffffffu, __float2uint_rn(sA));
        unsigned SB = __reduce_add_sync(0xffffffffu, __float2uint_rn(sB));
        unsigned SC = __reduce_add_sync(0xffffffffu, __float2uint_rn(sC));
        unsigned SD = __reduce_add_sync(0xffffffffu, __float2uint_rn(sD));
        unsigned SE = __reduce_add_sync(0xffffffffu, __float2uint_rn(sE));
        unsigned SF = __reduce_add_sync(0xffffffffu, __float2uint_rn(sF));

        row_tail(kmA, SA, evA, llA, sDiff);
        row_tail(kmB, SB, evB, llB, sDiff);
        row_tail(kmC, SC, evC, llC, sDiff);
        row_tail(kmD, SD, evD, llD, sDiff);
        row_tail(kmE, SE, evE, llE, sDiff);
        row_tail(kmF, SF, evF, llF, sDiff);
    }

    // ---- ragged tail: rows [nGrp*6, N), warp-per-row (<= 5 rows total) ----
    {
        int tailBase = nGrp * RPG;
        int tailCnt  = N - tailBase;
        if (gwarp < tailCnt) {
            int row = tailBase + gwarp;
            float4 v = NEG4;
            if (active)
                v = __ldg(base4 + (size_t)row * 25 + lane);
            int lbl = __ldg(labels + row);
            float em, s, ev; bool ll;
            row_core(v, lbl, lane, em, s, ev, ll);
            int km = __reduce_max_sync(0xffffffffu, __float_as_int(em));
            unsigned S = __reduce_add_sync(0xffffffffu, __float2uint_rn(s));
            row_tail(km, S, ev, ll, sDiff);
        }
    }

    // ---- block tail: partials -> global accumulator ----
    __syncthreads();
    if (tid < N_BINS)
        atomicAdd(&g_acc_diff[tid], sDiff[tid]);
    __threadfence();                      // publish before ticket
    if (tid == 0) sTicket = atomicAdd(&g_done, 1u);
    __syncthreads();

    // ---- last block finalizes, writes out, resets for next replay ----
    if (sTicket == GRID - 1) {
        __threadfence();                  // acquire: see all blocks' adds
        if (tid == 0) {
            float s = 0.0f;
            #pragma unroll
            for (int i = 0; i < N_BINS; i++)
                s += fabsf(g_acc_diff[i]);
            out[0] = s / (float)N;

            #pragma unroll
            for (int i = 0; i < 16; i++) g_acc_diff[i] = 0.0f;
            g_done = 0;                   // clean state for next graph replay
        }
    }
}

extern "C" void kernel_launch(void* const* d_in, const int* in_sizes, int n_in,
                              void* d_out, int out_size)
{
    const float* logits = (const float*)d_in[0];
    const int*   labels = (const int*)d_in[1];
    const int N = in_sizes[1];          // label count = number of rows

    ece_fused<<<GRID, TPB>>>(logits, labels, N, (float*)d_out);
}